// round 5
// baseline (speedup 1.0000x reference)
#include <cuda_runtime.h>
#include <cuda_bf16.h>
#include <cstdint>

// ============================================================
// Warp-MMA (mma.sync m16n8k16 bf16) flash attention, sm_100-safe.
// fp32 I/O, bf16 hi/lo split => 3 MMAs per GEMM product.
// b=8, n=m=4096, d=dv=64. BM=64 (4 warps x 16 rows), BN=64 keys/tile.
// Fixed-max softmax: p = exp2(qk*mq*log2e/T)*mk; O accumulated in regs.
// R5: ldmatrix.x4 (+.trans for V) B-fragment loads, 128B rows with XOR
// swizzle (conflict-free STS + ldmatrix), V stored row-major.
// ============================================================

namespace {
constexpr int NQ = 4096, NK = 4096, D = 64, DV = 64;
constexpr int BM = 64, BN = 64, THREADS = 128;
constexpr int NT = NK / BN;                     // 64 key tiles
constexpr float QSCALE = 0.18033688011112042f;  // log2(e) / 8
}

__device__ __forceinline__ uint32_t smem_u32(const void* p) {
  uint32_t a;
  asm("{ .reg .u64 t; cvta.to.shared.u64 t, %1; cvt.u32.u64 %0, t; }" : "=r"(a) : "l"(p));
  return a;
}
__device__ __forceinline__ uint32_t packbf2(__nv_bfloat16 a, __nv_bfloat16 b) {
  __nv_bfloat162 t = __halves2bfloat162(a, b);
  return *reinterpret_cast<uint32_t*>(&t);
}
__device__ __forceinline__ void split2(float x, float y, uint32_t& hi, uint32_t& lo) {
  __nv_bfloat16 hx = __float2bfloat16(x), hy = __float2bfloat16(y);
  hi = packbf2(hx, hy);
  lo = packbf2(__float2bfloat16(x - __bfloat162float(hx)),
               __float2bfloat16(y - __bfloat162float(hy)));
}
__device__ __forceinline__ float ex2f(float x) {
  float y;
  asm("ex2.approx.ftz.f32 %0, %1;" : "=f"(y) : "f"(x));
  return y;
}
__device__ __forceinline__ void mma16816(float* c, const uint32_t* a,
                                         uint32_t b0, uint32_t b1) {
  asm volatile(
    "mma.sync.aligned.m16n8k16.row.col.f32.bf16.bf16.f32 "
    "{%0,%1,%2,%3}, {%4,%5,%6,%7}, {%8,%9}, {%0,%1,%2,%3};"
    : "+f"(c[0]), "+f"(c[1]), "+f"(c[2]), "+f"(c[3])
    : "r"(a[0]), "r"(a[1]), "r"(a[2]), "r"(a[3]), "r"(b0), "r"(b1));
}
__device__ __forceinline__ void ldsm4(uint32_t a, uint32_t& d0, uint32_t& d1,
                                      uint32_t& d2, uint32_t& d3) {
  asm volatile("ldmatrix.sync.aligned.m8n8.x4.shared.b16 {%0,%1,%2,%3}, [%4];"
               : "=r"(d0), "=r"(d1), "=r"(d2), "=r"(d3) : "r"(a));
}
__device__ __forceinline__ void ldsm4t(uint32_t a, uint32_t& d0, uint32_t& d1,
                                       uint32_t& d2, uint32_t& d3) {
  asm volatile("ldmatrix.sync.aligned.m8n8.x4.trans.shared.b16 {%0,%1,%2,%3}, [%4];"
               : "=r"(d0), "=r"(d1), "=r"(d2), "=r"(d3) : "r"(a));
}
// 64x64 bf16 tile, 128B rows, XOR swizzle: elem (r,c) -> r*128 + (2c ^ ((r&7)*16))
__device__ __forceinline__ uint32_t swz(uint32_t r, uint32_t cbyte) {
  return r * 128u + (cbyte ^ ((r & 7u) * 16u));
}

__global__ __launch_bounds__(THREADS)
void attn_mma_kernel(const float* __restrict__ Q, const float* __restrict__ K,
                     const float* __restrict__ V, const int* __restrict__ MQ,
                     const int* __restrict__ MK, float* __restrict__ Out) {
  __shared__ alignas(128) char KsH[BN * 128];   // K hi, row-major [n][k], swizzled
  __shared__ alignas(128) char KsL[BN * 128];   // K lo
  __shared__ alignas(128) char VsH[BN * 128];   // V hi, row-major [c][dv], swizzled
  __shared__ alignas(128) char VsL[BN * 128];   // V lo
  __shared__ float mkf[BN];

  const int tid = threadIdx.x;
  const int w = tid >> 5, l = tid & 31;
  const int g = l >> 2, tg = l & 3;
  const int b = blockIdx.y;
  const int q0 = blockIdx.x * BM;
  const int row0 = q0 + w * 16 + g;
  const int row1 = row0 + 8;

  const uint32_t skh = smem_u32(KsH), skl = smem_u32(KsL);
  const uint32_t svh = smem_u32(VsH), svl = smem_u32(VsL);

  // ---- Q fragments (persistent). Fold mask * log2e/T into Q.
  uint32_t QH[4][4], QL[4][4];
  {
    const float* Qr0 = Q + ((size_t)b * NQ + row0) * D;
    const float* Qr1 = Q + ((size_t)b * NQ + row1) * D;
    const float m0 = MQ[(size_t)b * NQ + row0] ? QSCALE : 0.f;
    const float m1 = MQ[(size_t)b * NQ + row1] ? QSCALE : 0.f;
    #pragma unroll
    for (int ks = 0; ks < 4; ks++) {
      const int c = 16 * ks + 2 * tg;
      float2 v00 = *reinterpret_cast<const float2*>(Qr0 + c);
      float2 v10 = *reinterpret_cast<const float2*>(Qr1 + c);
      float2 v01 = *reinterpret_cast<const float2*>(Qr0 + c + 8);
      float2 v11 = *reinterpret_cast<const float2*>(Qr1 + c + 8);
      split2(v00.x * m0, v00.y * m0, QH[ks][0], QL[ks][0]);
      split2(v10.x * m1, v10.y * m1, QH[ks][1], QL[ks][1]);
      split2(v01.x * m0, v01.y * m0, QH[ks][2], QL[ks][2]);
      split2(v11.x * m1, v11.y * m1, QH[ks][3], QL[ks][3]);
    }
  }

  float O[8][4];
  #pragma unroll
  for (int i = 0; i < 8; i++)
    #pragma unroll
    for (int j = 0; j < 4; j++) O[i][j] = 0.f;
  float l0 = 0.f, l1 = 0.f;

  const float4* Kb = reinterpret_cast<const float4*>(K + (size_t)b * NK * D);
  const float4* Vb = reinterpret_cast<const float4*>(V + (size_t)b * NK * DV);
  const int* MKb = MK + (size_t)b * NK;

  // ldmatrix source addresses for this lane (byte offsets are tile-invariant)
  // K (non-trans): tile j = l>>3 at k-block, row n = 8*nf + (l&7)
  // V (trans):     tile j = l>>3 along c,   row c = kbase + 8*j + (l&7), colbyte 16*nf
  const uint32_t lrow = (uint32_t)(l & 7);
  const uint32_t ltile = (uint32_t)(l >> 3);

  for (int t = 0; t < NT; t++) {
    __syncthreads();

    // ---- K & V tiles -> smem (hi/lo), both row-major, swizzled, uint2 stores
    #pragma unroll
    for (int it = 0; it < 8; it++) {
      const int idx = tid + it * THREADS;
      const uint32_t r = (uint32_t)(idx >> 4), c4 = (uint32_t)((idx & 15) * 4);
      const uint32_t off = swz(r, c4 * 2);

      float4 kv = Kb[(size_t)t * BN * (D / 4) + idx];
      __nv_bfloat16 h0 = __float2bfloat16(kv.x), h1 = __float2bfloat16(kv.y);
      __nv_bfloat16 h2 = __float2bfloat16(kv.z), h3 = __float2bfloat16(kv.w);
      uint2 hw, lw;
      hw.x = packbf2(h0, h1); hw.y = packbf2(h2, h3);
      lw.x = packbf2(__float2bfloat16(kv.x - __bfloat162float(h0)),
                     __float2bfloat16(kv.y - __bfloat162float(h1)));
      lw.y = packbf2(__float2bfloat16(kv.z - __bfloat162float(h2)),
                     __float2bfloat16(kv.w - __bfloat162float(h3)));
      *reinterpret_cast<uint2*>(KsH + off) = hw;
      *reinterpret_cast<uint2*>(KsL + off) = lw;

      float4 vv = Vb[(size_t)t * BN * (DV / 4) + idx];
      h0 = __float2bfloat16(vv.x); h1 = __float2bfloat16(vv.y);
      h2 = __float2bfloat16(vv.z); h3 = __float2bfloat16(vv.w);
      hw.x = packbf2(h0, h1); hw.y = packbf2(h2, h3);
      lw.x = packbf2(__float2bfloat16(vv.x - __bfloat162float(h0)),
                     __float2bfloat16(vv.y - __bfloat162float(h1)));
      lw.y = packbf2(__float2bfloat16(vv.z - __bfloat162float(h2)),
                     __float2bfloat16(vv.w - __bfloat162float(h3)));
      *reinterpret_cast<uint2*>(VsH + off) = hw;
      *reinterpret_cast<uint2*>(VsL + off) = lw;
    }
    if (tid < BN) mkf[tid] = (float)MKb[t * BN + tid];
    __syncthreads();

    // ---- S = Q @ K^T  (3-MMA bf16 split, fp32 accum)
    float S[8][4];
    #pragma unroll
    for (int i = 0; i < 8; i++)
      #pragma unroll
      for (int j = 0; j < 4; j++) S[i][j] = 0.f;

    #pragma unroll
    for (int nf = 0; nf < 8; nf++) {
      const uint32_t n = 8u * nf + lrow;
      // tiles along k: j=l>>3 -> k-cols 8*j (+kbase). d0,d1 = b0,b1 for ks; d2,d3 next ks
      uint32_t a0 = swz(n, (0u + 8u * ltile) * 2u);
      uint32_t a1 = swz(n, (32u + 8u * ltile) * 2u);
      uint32_t bh[8], bl[8];
      ldsm4(skh + a0, bh[0], bh[1], bh[2], bh[3]);
      ldsm4(skh + a1, bh[4], bh[5], bh[6], bh[7]);
      ldsm4(skl + a0, bl[0], bl[1], bl[2], bl[3]);
      ldsm4(skl + a1, bl[4], bl[5], bl[6], bl[7]);
      #pragma unroll
      for (int ks = 0; ks < 4; ks++) {
        mma16816(S[nf], QH[ks], bh[2 * ks], bh[2 * ks + 1]);
        mma16816(S[nf], QH[ks], bl[2 * ks], bl[2 * ks + 1]);
        mma16816(S[nf], QL[ks], bh[2 * ks], bh[2 * ks + 1]);
      }
    }

    // ---- softmax: p = exp2(S) * mk  (S already has log2e/T and query mask)
    #pragma unroll
    for (int nf = 0; nf < 8; nf++) {
      const int c0 = 8 * nf + 2 * tg;
      const float mk0 = mkf[c0], mk1 = mkf[c0 + 1];
      float p0 = ex2f(S[nf][0]) * mk0;
      float p1 = ex2f(S[nf][1]) * mk1;
      float p2 = ex2f(S[nf][2]) * mk0;
      float p3 = ex2f(S[nf][3]) * mk1;
      l0 += p0 + p1; l1 += p2 + p3;
      S[nf][0] = p0; S[nf][1] = p1; S[nf][2] = p2; S[nf][3] = p3;
    }

    // ---- repack P: S-accumulator fragment layout == A-operand layout
    uint32_t PH[4][4], PL[4][4];
    #pragma unroll
    for (int kc = 0; kc < 4; kc++) {
      split2(S[2 * kc][0],     S[2 * kc][1],     PH[kc][0], PL[kc][0]);
      split2(S[2 * kc][2],     S[2 * kc][3],     PH[kc][1], PL[kc][1]);
      split2(S[2 * kc + 1][0], S[2 * kc + 1][1], PH[kc][2], PL[kc][2]);
      split2(S[2 * kc + 1][2], S[2 * kc + 1][3], PH[kc][3], PL[kc][3]);
    }

    // ---- O += P @ V  (V row-major; transposed fragments via ldmatrix.trans)
    #pragma unroll
    for (int nf = 0; nf < 8; nf++) {
      // tile j = l>>3 along c: rows c = kbase + 8*j + (l&7); col-block dv = 8*nf
      const uint32_t r0 = 0u + 8u * ltile + lrow;
      const uint32_t r1 = 32u + 8u * ltile + lrow;
      uint32_t a0 = swz(r0, 16u * nf);
      uint32_t a1 = swz(r1, 16u * nf);
      uint32_t bh[8], bl[8];
      ldsm4t(svh + a0, bh[0], bh[1], bh[2], bh[3]);
      ldsm4t(svh + a1, bh[4], bh[5], bh[6], bh[7]);
      ldsm4t(svl + a0, bl[0], bl[1], bl[2], bl[3]);
      ldsm4t(svl + a1, bl[4], bl[5], bl[6], bl[7]);
      #pragma unroll
      for (int kc = 0; kc < 4; kc++) {
        mma16816(O[nf], PH[kc], bh[2 * kc], bh[2 * kc + 1]);
        mma16816(O[nf], PL[kc], bh[2 * kc], bh[2 * kc + 1]);
        mma16816(O[nf], PH[kc], bl[2 * kc], bl[2 * kc + 1]);
      }
    }
  }

  // ---- finalize
  l0 += __shfl_xor_sync(0xffffffffu, l0, 1);
  l0 += __shfl_xor_sync(0xffffffffu, l0, 2);
  l1 += __shfl_xor_sync(0xffffffffu, l1, 1);
  l1 += __shfl_xor_sync(0xffffffffu, l1, 2);
  const float inv0 = 1.0f / l0, inv1 = 1.0f / l1;

  float* O0 = Out + ((size_t)b * NQ + row0) * DV;
  float* O1 = Out + ((size_t)b * NQ + row1) * DV;
  #pragma unroll
  for (int nf = 0; nf < 8; nf++) {
    const int c = 8 * nf + 2 * tg;
    *reinterpret_cast<float2*>(O0 + c) = make_float2(O[nf][0] * inv0, O[nf][1] * inv0);
    *reinterpret_cast<float2*>(O1 + c) = make_float2(O[nf][2] * inv1, O[nf][3] * inv1);
  }
}

extern "C" void kernel_launch(void* const* d_in, const int* in_sizes, int n_in,
                              void* d_out, int out_size) {
  (void)in_sizes; (void)n_in; (void)out_size;
  const float* Q  = (const float*)d_in[0];
  const float* K  = (const float*)d_in[1];
  const float* V  = (const float*)d_in[2];
  const int*   MQ = (const int*)d_in[3];
  const int*   MK = (const int*)d_in[4];
  float* Out = (float*)d_out;

  dim3 grid(NQ / BM, 8);
  attn_mma_kernel<<<grid, THREADS>>>(Q, K, V, MQ, MK, Out);
}

// round 6
// speedup vs baseline: 1.3318x; 1.3318x over previous
#include <cuda_runtime.h>
#include <cuda_bf16.h>
#include <cstdint>

// ============================================================
// Warp-MMA (mma.sync m16n8k16 bf16) flash attention, sm_100-safe.
// fp32 I/O, bf16 hi/lo split => 3 MMAs per GEMM product.
// b=8, n=m=4096, d=dv=64. BM=128 (8 warps x 16 rows), BN=64 keys/tile.
// Fixed-max softmax: p = exp2(qk*mq*log2e/T)*mk; O accumulated in regs.
// R6: ldmatrix fragment loads kept from R5, but (a) hi/lo fragment batches
// sequenced to halve live registers, (b) 128-reg cap via launch_bounds,
// (c) BM=128/256 threads to amortize K/V load+convert work.
// ============================================================

namespace {
constexpr int NQ = 4096, NK = 4096, D = 64, DV = 64;
constexpr int BM = 128, BN = 64, THREADS = 256;
constexpr int NT = NK / BN;                     // 64 key tiles
constexpr float QSCALE = 0.18033688011112042f;  // log2(e) / 8
}

__device__ __forceinline__ uint32_t smem_u32(const void* p) {
  uint32_t a;
  asm("{ .reg .u64 t; cvta.to.shared.u64 t, %1; cvt.u32.u64 %0, t; }" : "=r"(a) : "l"(p));
  return a;
}
__device__ __forceinline__ uint32_t packbf2(__nv_bfloat16 a, __nv_bfloat16 b) {
  __nv_bfloat162 t = __halves2bfloat162(a, b);
  return *reinterpret_cast<uint32_t*>(&t);
}
__device__ __forceinline__ void split2(float x, float y, uint32_t& hi, uint32_t& lo) {
  __nv_bfloat16 hx = __float2bfloat16(x), hy = __float2bfloat16(y);
  hi = packbf2(hx, hy);
  lo = packbf2(__float2bfloat16(x - __bfloat162float(hx)),
               __float2bfloat16(y - __bfloat162float(hy)));
}
__device__ __forceinline__ float ex2f(float x) {
  float y;
  asm("ex2.approx.ftz.f32 %0, %1;" : "=f"(y) : "f"(x));
  return y;
}
__device__ __forceinline__ void mma16816(float* c, const uint32_t* a,
                                         uint32_t b0, uint32_t b1) {
  asm volatile(
    "mma.sync.aligned.m16n8k16.row.col.f32.bf16.bf16.f32 "
    "{%0,%1,%2,%3}, {%4,%5,%6,%7}, {%8,%9}, {%0,%1,%2,%3};"
    : "+f"(c[0]), "+f"(c[1]), "+f"(c[2]), "+f"(c[3])
    : "r"(a[0]), "r"(a[1]), "r"(a[2]), "r"(a[3]), "r"(b0), "r"(b1));
}
__device__ __forceinline__ void ldsm4(uint32_t a, uint32_t* d) {
  asm volatile("ldmatrix.sync.aligned.m8n8.x4.shared.b16 {%0,%1,%2,%3}, [%4];"
               : "=r"(d[0]), "=r"(d[1]), "=r"(d[2]), "=r"(d[3]) : "r"(a));
}
__device__ __forceinline__ void ldsm4t(uint32_t a, uint32_t* d) {
  asm volatile("ldmatrix.sync.aligned.m8n8.x4.trans.shared.b16 {%0,%1,%2,%3}, [%4];"
               : "=r"(d[0]), "=r"(d[1]), "=r"(d[2]), "=r"(d[3]) : "r"(a));
}
// 64x64 bf16 tile, 128B rows, XOR swizzle: elem (r,c) -> r*128 + (2c ^ ((r&7)*16))
__device__ __forceinline__ uint32_t swz(uint32_t r, uint32_t cbyte) {
  return r * 128u + (cbyte ^ ((r & 7u) * 16u));
}

__global__ __launch_bounds__(THREADS, 2)
void attn_mma_kernel(const float* __restrict__ Q, const float* __restrict__ K,
                     const float* __restrict__ V, const int* __restrict__ MQ,
                     const int* __restrict__ MK, float* __restrict__ Out) {
  __shared__ alignas(128) char KsH[BN * 128];   // K hi, row-major [n][k], swizzled
  __shared__ alignas(128) char KsL[BN * 128];   // K lo
  __shared__ alignas(128) char VsH[BN * 128];   // V hi, row-major [c][dv], swizzled
  __shared__ alignas(128) char VsL[BN * 128];   // V lo
  __shared__ float mkf[BN];

  const int tid = threadIdx.x;
  const int w = tid >> 5, l = tid & 31;
  const int g = l >> 2, tg = l & 3;
  const int b = blockIdx.y;
  const int q0 = blockIdx.x * BM;
  const int row0 = q0 + w * 16 + g;
  const int row1 = row0 + 8;

  const uint32_t skh = smem_u32(KsH), skl = smem_u32(KsL);
  const uint32_t svh = smem_u32(VsH), svl = smem_u32(VsL);
  const uint32_t lrow = (uint32_t)(l & 7);
  const uint32_t ltile = (uint32_t)(l >> 3);

  // ---- Q fragments (persistent). Fold mask * log2e/T into Q.
  uint32_t QH[4][4], QL[4][4];
  {
    const float* Qr0 = Q + ((size_t)b * NQ + row0) * D;
    const float* Qr1 = Q + ((size_t)b * NQ + row1) * D;
    const float m0 = MQ[(size_t)b * NQ + row0] ? QSCALE : 0.f;
    const float m1 = MQ[(size_t)b * NQ + row1] ? QSCALE : 0.f;
    #pragma unroll
    for (int ks = 0; ks < 4; ks++) {
      const int c = 16 * ks + 2 * tg;
      float2 v00 = *reinterpret_cast<const float2*>(Qr0 + c);
      float2 v10 = *reinterpret_cast<const float2*>(Qr1 + c);
      float2 v01 = *reinterpret_cast<const float2*>(Qr0 + c + 8);
      float2 v11 = *reinterpret_cast<const float2*>(Qr1 + c + 8);
      split2(v00.x * m0, v00.y * m0, QH[ks][0], QL[ks][0]);
      split2(v10.x * m1, v10.y * m1, QH[ks][1], QL[ks][1]);
      split2(v01.x * m0, v01.y * m0, QH[ks][2], QL[ks][2]);
      split2(v11.x * m1, v11.y * m1, QH[ks][3], QL[ks][3]);
    }
  }

  float O[8][4];
  #pragma unroll
  for (int i = 0; i < 8; i++)
    #pragma unroll
    for (int j = 0; j < 4; j++) O[i][j] = 0.f;
  float l0 = 0.f, l1 = 0.f;

  const float4* Kb = reinterpret_cast<const float4*>(K + (size_t)b * NK * D);
  const float4* Vb = reinterpret_cast<const float4*>(V + (size_t)b * NK * DV);
  const int* MKb = MK + (size_t)b * NK;

  for (int t = 0; t < NT; t++) {
    __syncthreads();

    // ---- K & V tiles -> smem (hi/lo), row-major, swizzled, uint2 stores.
    // 1024 float4 per tensor, 256 threads -> 4 iterations each.
    #pragma unroll
    for (int it = 0; it < 4; it++) {
      const int idx = tid + it * THREADS;
      const uint32_t r = (uint32_t)(idx >> 4), c4 = (uint32_t)((idx & 15) * 4);
      const uint32_t off = swz(r, c4 * 2);

      float4 kv = Kb[(size_t)t * BN * (D / 4) + idx];
      __nv_bfloat16 h0 = __float2bfloat16(kv.x), h1 = __float2bfloat16(kv.y);
      __nv_bfloat16 h2 = __float2bfloat16(kv.z), h3 = __float2bfloat16(kv.w);
      uint2 hw, lw;
      hw.x = packbf2(h0, h1); hw.y = packbf2(h2, h3);
      lw.x = packbf2(__float2bfloat16(kv.x - __bfloat162float(h0)),
                     __float2bfloat16(kv.y - __bfloat162float(h1)));
      lw.y = packbf2(__float2bfloat16(kv.z - __bfloat162float(h2)),
                     __float2bfloat16(kv.w - __bfloat162float(h3)));
      *reinterpret_cast<uint2*>(KsH + off) = hw;
      *reinterpret_cast<uint2*>(KsL + off) = lw;

      float4 vv = Vb[(size_t)t * BN * (DV / 4) + idx];
      h0 = __float2bfloat16(vv.x); h1 = __float2bfloat16(vv.y);
      h2 = __float2bfloat16(vv.z); h3 = __float2bfloat16(vv.w);
      hw.x = packbf2(h0, h1); hw.y = packbf2(h2, h3);
      lw.x = packbf2(__float2bfloat16(vv.x - __bfloat162float(h0)),
                     __float2bfloat16(vv.y - __bfloat162float(h1)));
      lw.y = packbf2(__float2bfloat16(vv.z - __bfloat162float(h2)),
                     __float2bfloat16(vv.w - __bfloat162float(h3)));
      *reinterpret_cast<uint2*>(VsH + off) = hw;
      *reinterpret_cast<uint2*>(VsL + off) = lw;
    }
    if (tid < BN) mkf[tid] = (float)MKb[t * BN + tid];
    __syncthreads();

    // ---- S = Q @ K^T  (hi-batch then lo-batch: peak 8 frag regs)
    float S[8][4];
    #pragma unroll
    for (int i = 0; i < 8; i++)
      #pragma unroll
      for (int j = 0; j < 4; j++) S[i][j] = 0.f;

    #pragma unroll
    for (int nf = 0; nf < 8; nf++) {
      const uint32_t n = 8u * nf + lrow;
      const uint32_t a0 = swz(n, (8u * ltile) * 2u);
      const uint32_t a1 = swz(n, (32u + 8u * ltile) * 2u);
      uint32_t f[8];
      ldsm4(skh + a0, f);          // K hi, ks=0..1
      ldsm4(skh + a1, f + 4);      // K hi, ks=2..3
      #pragma unroll
      for (int ks = 0; ks < 4; ks++) {
        mma16816(S[nf], QH[ks], f[2 * ks], f[2 * ks + 1]);
        mma16816(S[nf], QL[ks], f[2 * ks], f[2 * ks + 1]);
      }
      ldsm4(skl + a0, f);          // K lo (reuse regs)
      ldsm4(skl + a1, f + 4);
      #pragma unroll
      for (int ks = 0; ks < 4; ks++)
        mma16816(S[nf], QH[ks], f[2 * ks], f[2 * ks + 1]);
    }

    // ---- softmax: p = exp2(S) * mk
    #pragma unroll
    for (int nf = 0; nf < 8; nf++) {
      const int c0 = 8 * nf + 2 * tg;
      const float mk0 = mkf[c0], mk1 = mkf[c0 + 1];
      float p0 = ex2f(S[nf][0]) * mk0;
      float p1 = ex2f(S[nf][1]) * mk1;
      float p2 = ex2f(S[nf][2]) * mk0;
      float p3 = ex2f(S[nf][3]) * mk1;
      l0 += p0 + p1; l1 += p2 + p3;
      S[nf][0] = p0; S[nf][1] = p1; S[nf][2] = p2; S[nf][3] = p3;
    }

    // ---- repack P: S-accumulator fragment layout == A-operand layout
    uint32_t PH[4][4], PL[4][4];
    #pragma unroll
    for (int kc = 0; kc < 4; kc++) {
      split2(S[2 * kc][0],     S[2 * kc][1],     PH[kc][0], PL[kc][0]);
      split2(S[2 * kc][2],     S[2 * kc][3],     PH[kc][1], PL[kc][1]);
      split2(S[2 * kc + 1][0], S[2 * kc + 1][1], PH[kc][2], PL[kc][2]);
      split2(S[2 * kc + 1][2], S[2 * kc + 1][3], PH[kc][3], PL[kc][3]);
    }

    // ---- O += P @ V  (trans fragments; hi-batch then lo-batch)
    #pragma unroll
    for (int nf = 0; nf < 8; nf++) {
      const uint32_t r0 = 8u * ltile + lrow;
      const uint32_t r1 = 32u + 8u * ltile + lrow;
      const uint32_t a0 = swz(r0, 16u * nf);
      const uint32_t a1 = swz(r1, 16u * nf);
      uint32_t f[8];
      ldsm4t(svh + a0, f);         // V hi, kc=0..1
      ldsm4t(svh + a1, f + 4);     // V hi, kc=2..3
      #pragma unroll
      for (int kc = 0; kc < 4; kc++) {
        mma16816(O[nf], PH[kc], f[2 * kc], f[2 * kc + 1]);
        mma16816(O[nf], PL[kc], f[2 * kc], f[2 * kc + 1]);
      }
      ldsm4t(svl + a0, f);         // V lo (reuse regs)
      ldsm4t(svl + a1, f + 4);
      #pragma unroll
      for (int kc = 0; kc < 4; kc++)
        mma16816(O[nf], PH[kc], f[2 * kc], f[2 * kc + 1]);
    }
  }

  // ---- finalize
  l0 += __shfl_xor_sync(0xffffffffu, l0, 1);
  l0 += __shfl_xor_sync(0xffffffffu, l0, 2);
  l1 += __shfl_xor_sync(0xffffffffu, l1, 1);
  l1 += __shfl_xor_sync(0xffffffffu, l1, 2);
  const float inv0 = 1.0f / l0, inv1 = 1.0f / l1;

  float* O0 = Out + ((size_t)b * NQ + row0) * DV;
  float* O1 = Out + ((size_t)b * NQ + row1) * DV;
  #pragma unroll
  for (int nf = 0; nf < 8; nf++) {
    const int c = 8 * nf + 2 * tg;
    *reinterpret_cast<float2*>(O0 + c) = make_float2(O[nf][0] * inv0, O[nf][1] * inv0);
    *reinterpret_cast<float2*>(O1 + c) = make_float2(O[nf][2] * inv1, O[nf][3] * inv1);
  }
}

extern "C" void kernel_launch(void* const* d_in, const int* in_sizes, int n_in,
                              void* d_out, int out_size) {
  (void)in_sizes; (void)n_in; (void)out_size;
  const float* Q  = (const float*)d_in[0];
  const float* K  = (const float*)d_in[1];
  const float* V  = (const float*)d_in[2];
  const int*   MQ = (const int*)d_in[3];
  const int*   MK = (const int*)d_in[4];
  float* Out = (float*)d_out;

  dim3 grid(NQ / BM, 8);
  attn_mma_kernel<<<grid, THREADS>>>(Q, K, V, MQ, MK, Out);
}

// round 7
// speedup vs baseline: 1.4172x; 1.0641x over previous
#include <cuda_runtime.h>
#include <cuda_bf16.h>
#include <cstdint>

// ============================================================
// R7: two-kernel scheme.
//  1) convert_kernel: K,V fp32 -> bf16 hi/lo, stored once in __device__
//     scratch in the swizzled CTA-tile smem layout (per 64-row tile).
//  2) attn kernel: cp.async 16B double-buffered tile fetch (no convert,
//     no STS in hot loop), warp-MMA m16n8k16 bf16 3-product split,
//     fixed-max softmax, O accumulated in registers.
// b=8, n=m=4096, d=dv=64. BM=128 (8 warps), BN=64, 256 threads.
// ============================================================

namespace {
constexpr int NQ = 4096, NK = 4096, D = 64, DV = 64, Bb = 8;
constexpr int BM = 128, BN = 64, THREADS = 256;
constexpr int NT = NK / BN;                     // 64 key tiles per batch
constexpr float QSCALE = 0.18033688011112042f;  // log2(e) / 8

// per-stage smem layout (bytes)
constexpr int ST_KH = 0, ST_KL = 8192, ST_VH = 16384, ST_VL = 24576, ST_MK = 32768;
constexpr int STAGE = 33024;                    // 4*8192 + 256
constexpr int SMEM_BYTES = 2 * STAGE;           // 66048
}

// 16 MB conversion scratch: [b*64+t] tiles of 8192 B, swizzled layout
__device__ __align__(16) uint8_t g_KH[(size_t)Bb * NK * D * 2];
__device__ __align__(16) uint8_t g_KL[(size_t)Bb * NK * D * 2];
__device__ __align__(16) uint8_t g_VH[(size_t)Bb * NK * DV * 2];
__device__ __align__(16) uint8_t g_VL[(size_t)Bb * NK * DV * 2];

__device__ __forceinline__ uint32_t smem_u32(const void* p) {
  uint32_t a;
  asm("{ .reg .u64 t; cvta.to.shared.u64 t, %1; cvt.u32.u64 %0, t; }" : "=r"(a) : "l"(p));
  return a;
}
__device__ __forceinline__ uint32_t packbf2(__nv_bfloat16 a, __nv_bfloat16 b) {
  __nv_bfloat162 t = __halves2bfloat162(a, b);
  return *reinterpret_cast<uint32_t*>(&t);
}
__device__ __forceinline__ void split2(float x, float y, uint32_t& hi, uint32_t& lo) {
  __nv_bfloat16 hx = __float2bfloat16(x), hy = __float2bfloat16(y);
  hi = packbf2(hx, hy);
  lo = packbf2(__float2bfloat16(x - __bfloat162float(hx)),
               __float2bfloat16(y - __bfloat162float(hy)));
}
__device__ __forceinline__ float ex2f(float x) {
  float y;
  asm("ex2.approx.ftz.f32 %0, %1;" : "=f"(y) : "f"(x));
  return y;
}
__device__ __forceinline__ void mma16816(float* c, const uint32_t* a,
                                         uint32_t b0, uint32_t b1) {
  asm volatile(
    "mma.sync.aligned.m16n8k16.row.col.f32.bf16.bf16.f32 "
    "{%0,%1,%2,%3}, {%4,%5,%6,%7}, {%8,%9}, {%0,%1,%2,%3};"
    : "+f"(c[0]), "+f"(c[1]), "+f"(c[2]), "+f"(c[3])
    : "r"(a[0]), "r"(a[1]), "r"(a[2]), "r"(a[3]), "r"(b0), "r"(b1));
}
__device__ __forceinline__ void ldsm4(uint32_t a, uint32_t* d) {
  asm volatile("ldmatrix.sync.aligned.m8n8.x4.shared.b16 {%0,%1,%2,%3}, [%4];"
               : "=r"(d[0]), "=r"(d[1]), "=r"(d[2]), "=r"(d[3]) : "r"(a));
}
__device__ __forceinline__ void ldsm4t(uint32_t a, uint32_t* d) {
  asm volatile("ldmatrix.sync.aligned.m8n8.x4.trans.shared.b16 {%0,%1,%2,%3}, [%4];"
               : "=r"(d[0]), "=r"(d[1]), "=r"(d[2]), "=r"(d[3]) : "r"(a));
}
__device__ __forceinline__ void cpasync16(uint32_t dst, const void* src) {
  asm volatile("cp.async.cg.shared.global [%0], [%1], 16;"
               :: "r"(dst), "l"(src) : "memory");
}
#define CP_COMMIT() asm volatile("cp.async.commit_group;" ::: "memory")
#define CP_WAIT1()  asm volatile("cp.async.wait_group 1;"  ::: "memory")

// 64x64 bf16 tile, 128B rows, XOR swizzle: elem (r,c) -> r*128 + (2c ^ ((r&7)*16))
__device__ __forceinline__ uint32_t swz(uint32_t r, uint32_t cbyte) {
  return r * 128u + (cbyte ^ ((r & 7u) * 16u));
}

// ---------------- pre-pass: fp32 K,V -> bf16 hi/lo, swizzled tiles ----------------
__global__ __launch_bounds__(256)
void convert_kernel(const float* __restrict__ K, const float* __restrict__ V) {
  const int idx = blockIdx.x * 256 + threadIdx.x;   // one float4 of K and of V
  const int n = idx >> 4;                           // global row (b*4096 + key)
  const int c4 = idx & 15;
  const uint32_t r = (uint32_t)(n & 63);
  const size_t tbase = (size_t)(n >> 6) * 8192;     // (b*64 + t) * tile_bytes
  const size_t off = tbase + swz(r, (uint32_t)c4 * 8u);

  float4 kv = reinterpret_cast<const float4*>(K)[idx];
  uint2 hw, lw;
  split2(kv.x, kv.y, hw.x, lw.x);
  split2(kv.z, kv.w, hw.y, lw.y);
  *reinterpret_cast<uint2*>(g_KH + off) = hw;
  *reinterpret_cast<uint2*>(g_KL + off) = lw;

  float4 vv = reinterpret_cast<const float4*>(V)[idx];
  split2(vv.x, vv.y, hw.x, lw.x);
  split2(vv.z, vv.w, hw.y, lw.y);
  *reinterpret_cast<uint2*>(g_VH + off) = hw;
  *reinterpret_cast<uint2*>(g_VL + off) = lw;
}

// ---------------- main attention kernel ----------------
__global__ __launch_bounds__(THREADS, 2)
void attn_mma_kernel(const float* __restrict__ Q, const int* __restrict__ MQ,
                     const int* __restrict__ MK, float* __restrict__ Out) {
  extern __shared__ char smem[];
  const uint32_t sb = smem_u32(smem);

  const int tid = threadIdx.x;
  const int w = tid >> 5, l = tid & 31;
  const int g = l >> 2, tg = l & 3;
  const int b = blockIdx.y;
  const int q0 = blockIdx.x * BM;
  const int row0 = q0 + w * 16 + g;
  const int row1 = row0 + 8;
  const uint32_t lrow = (uint32_t)(l & 7);
  const uint32_t ltile = (uint32_t)(l >> 3);
  const int* MKb = MK + (size_t)b * NK;

  // ---- Q fragments (persistent). Fold mask * log2e/T into Q.
  uint32_t QH[4][4], QL[4][4];
  {
    const float* Qr0 = Q + ((size_t)b * NQ + row0) * D;
    const float* Qr1 = Q + ((size_t)b * NQ + row1) * D;
    const float m0 = MQ[(size_t)b * NQ + row0] ? QSCALE : 0.f;
    const float m1 = MQ[(size_t)b * NQ + row1] ? QSCALE : 0.f;
    #pragma unroll
    for (int ks = 0; ks < 4; ks++) {
      const int c = 16 * ks + 2 * tg;
      float2 v00 = *reinterpret_cast<const float2*>(Qr0 + c);
      float2 v10 = *reinterpret_cast<const float2*>(Qr1 + c);
      float2 v01 = *reinterpret_cast<const float2*>(Qr0 + c + 8);
      float2 v11 = *reinterpret_cast<const float2*>(Qr1 + c + 8);
      split2(v00.x * m0, v00.y * m0, QH[ks][0], QL[ks][0]);
      split2(v10.x * m1, v10.y * m1, QH[ks][1], QL[ks][1]);
      split2(v01.x * m0, v01.y * m0, QH[ks][2], QL[ks][2]);
      split2(v11.x * m1, v11.y * m1, QH[ks][3], QL[ks][3]);
    }
  }

  float O[8][4];
  #pragma unroll
  for (int i = 0; i < 8; i++)
    #pragma unroll
    for (int j = 0; j < 4; j++) O[i][j] = 0.f;
  float l0 = 0.f, l1 = 0.f;

  // ---- prefetch helper: tile t -> stage s (pre-swizzled gmem, linear copy)
  auto prefetch = [&](int t, int s) {
    const uint32_t dst = sb + (uint32_t)s * STAGE;
    const size_t toff = (size_t)(b * NT + t) * 8192;
    #pragma unroll
    for (int i = 0; i < 2; i++) {
      const uint32_t o = (uint32_t)(tid + i * THREADS) * 16u;
      cpasync16(dst + ST_KH + o, g_KH + toff + o);
      cpasync16(dst + ST_KL + o, g_KL + toff + o);
      cpasync16(dst + ST_VH + o, g_VH + toff + o);
      cpasync16(dst + ST_VL + o, g_VL + toff + o);
    }
    if (tid < 16) cpasync16(dst + ST_MK + tid * 16u, MKb + t * BN + tid * 4);
  };

  prefetch(0, 0);
  CP_COMMIT();

  for (int t = 0; t < NT; t++) {
    const int s = t & 1;
    if (t + 1 < NT) prefetch(t + 1, (t + 1) & 1);
    CP_COMMIT();          // uniform group accounting (empty group on last iter)
    CP_WAIT1();           // stage s complete
    __syncthreads();

    const uint32_t skh = sb + (uint32_t)s * STAGE + ST_KH;
    const uint32_t skl = sb + (uint32_t)s * STAGE + ST_KL;
    const uint32_t svh = sb + (uint32_t)s * STAGE + ST_VH;
    const uint32_t svl = sb + (uint32_t)s * STAGE + ST_VL;
    const int* mki = reinterpret_cast<const int*>(smem + (size_t)s * STAGE + ST_MK);

    // ---- S = Q @ K^T  (hi-batch then lo-batch; peak 8 frag regs)
    float S[8][4];
    #pragma unroll
    for (int i = 0; i < 8; i++)
      #pragma unroll
      for (int j = 0; j < 4; j++) S[i][j] = 0.f;

    #pragma unroll
    for (int nf = 0; nf < 8; nf++) {
      const uint32_t n = 8u * nf + lrow;
      const uint32_t a0 = swz(n, (8u * ltile) * 2u);
      const uint32_t a1 = swz(n, (32u + 8u * ltile) * 2u);
      uint32_t f[8];
      ldsm4(skh + a0, f);
      ldsm4(skh + a1, f + 4);
      #pragma unroll
      for (int ks = 0; ks < 4; ks++) {
        mma16816(S[nf], QH[ks], f[2 * ks], f[2 * ks + 1]);
        mma16816(S[nf], QL[ks], f[2 * ks], f[2 * ks + 1]);
      }
      ldsm4(skl + a0, f);
      ldsm4(skl + a1, f + 4);
      #pragma unroll
      for (int ks = 0; ks < 4; ks++)
        mma16816(S[nf], QH[ks], f[2 * ks], f[2 * ks + 1]);
    }

    // ---- softmax: p = exp2(S) * mk
    #pragma unroll
    for (int nf = 0; nf < 8; nf++) {
      const int c0 = 8 * nf + 2 * tg;
      const float mk0 = (float)mki[c0], mk1 = (float)mki[c0 + 1];
      float p0 = ex2f(S[nf][0]) * mk0;
      float p1 = ex2f(S[nf][1]) * mk1;
      float p2 = ex2f(S[nf][2]) * mk0;
      float p3 = ex2f(S[nf][3]) * mk1;
      l0 += p0 + p1; l1 += p2 + p3;
      S[nf][0] = p0; S[nf][1] = p1; S[nf][2] = p2; S[nf][3] = p3;
    }

    // ---- repack P: S-accumulator fragment layout == A-operand layout
    uint32_t PH[4][4], PL[4][4];
    #pragma unroll
    for (int kc = 0; kc < 4; kc++) {
      split2(S[2 * kc][0],     S[2 * kc][1],     PH[kc][0], PL[kc][0]);
      split2(S[2 * kc][2],     S[2 * kc][3],     PH[kc][1], PL[kc][1]);
      split2(S[2 * kc + 1][0], S[2 * kc + 1][1], PH[kc][2], PL[kc][2]);
      split2(S[2 * kc + 1][2], S[2 * kc + 1][3], PH[kc][3], PL[kc][3]);
    }

    // ---- O += P @ V  (trans fragments; hi-batch then lo-batch)
    #pragma unroll
    for (int nf = 0; nf < 8; nf++) {
      const uint32_t r0 = 8u * ltile + lrow;
      const uint32_t r1 = 32u + 8u * ltile + lrow;
      const uint32_t a0 = swz(r0, 16u * nf);
      const uint32_t a1 = swz(r1, 16u * nf);
      uint32_t f[8];
      ldsm4t(svh + a0, f);
      ldsm4t(svh + a1, f + 4);
      #pragma unroll
      for (int kc = 0; kc < 4; kc++) {
        mma16816(O[nf], PH[kc], f[2 * kc], f[2 * kc + 1]);
        mma16816(O[nf], PL[kc], f[2 * kc], f[2 * kc + 1]);
      }
      ldsm4t(svl + a0, f);
      ldsm4t(svl + a1, f + 4);
      #pragma unroll
      for (int kc = 0; kc < 4; kc++)
        mma16816(O[nf], PH[kc], f[2 * kc], f[2 * kc + 1]);
    }
    __syncthreads();   // all reads of stage s done before it is refilled (t+2)
  }

  // ---- finalize
  l0 += __shfl_xor_sync(0xffffffffu, l0, 1);
  l0 += __shfl_xor_sync(0xffffffffu, l0, 2);
  l1 += __shfl_xor_sync(0xffffffffu, l1, 1);
  l1 += __shfl_xor_sync(0xffffffffu, l1, 2);
  const float inv0 = 1.0f / l0, inv1 = 1.0f / l1;

  float* O0 = Out + ((size_t)b * NQ + row0) * DV;
  float* O1 = Out + ((size_t)b * NQ + row1) * DV;
  #pragma unroll
  for (int nf = 0; nf < 8; nf++) {
    const int c = 8 * nf + 2 * tg;
    *reinterpret_cast<float2*>(O0 + c) = make_float2(O[nf][0] * inv0, O[nf][1] * inv0);
    *reinterpret_cast<float2*>(O1 + c) = make_float2(O[nf][2] * inv1, O[nf][3] * inv1);
  }
}

extern "C" void kernel_launch(void* const* d_in, const int* in_sizes, int n_in,
                              void* d_out, int out_size) {
  (void)in_sizes; (void)n_in; (void)out_size;
  const float* Q  = (const float*)d_in[0];
  const float* K  = (const float*)d_in[1];
  const float* V  = (const float*)d_in[2];
  const int*   MQ = (const int*)d_in[3];
  const int*   MK = (const int*)d_in[4];
  float* Out = (float*)d_out;

  // pre-pass: 8*4096*16 float4 slots / 256 threads
  convert_kernel<<<(Bb * NK * (D / 4)) / 256, 256>>>(K, V);

  cudaFuncSetAttribute(attn_mma_kernel,
                       cudaFuncAttributeMaxDynamicSharedMemorySize, SMEM_BYTES);
  dim3 grid(NQ / BM, Bb);
  attn_mma_kernel<<<grid, THREADS, SMEM_BYTES>>>(Q, MQ, MK, Out);
}

// round 9
// speedup vs baseline: 1.5762x; 1.1122x over previous
#include <cuda_runtime.h>
#include <cuda_bf16.h>
#include <cstdint>

// ============================================================
// R9 (= R8 resubmission): split-K=4 flash attention for load balance.
//  1) convert_kernel: K,V fp32 -> bf16 hi/lo once, swizzled 64-row tiles.
//  2) attn kernel: grid (32, 8, 4) = 1024 CTAs; each handles 16 key tiles.
//     Fixed-max softmax => O and l additive across quarters.
//  3) combine_kernel: Out = sum_z O_z / sum_z l_z.
// Mainloop identical to R7 (305 us, tensor 61%): cp.async double buffer,
// mma m16n8k16 bf16 3-product hi/lo split, 128-reg cap, 2 CTAs/SM.
// ============================================================

namespace {
constexpr int NQ = 4096, NK = 4096, D = 64, DV = 64, Bb = 8;
constexpr int BM = 128, BN = 64, THREADS = 256;
constexpr int NT = NK / BN;                     // 64 key tiles total
constexpr int NSPLIT = 4;
constexpr int NTQ = NT / NSPLIT;                // 16 tiles per quarter
constexpr float QSCALE = 0.18033688011112042f;  // log2(e) / 8

constexpr int ST_KH = 0, ST_KL = 8192, ST_VH = 16384, ST_VL = 24576, ST_MK = 32768;
constexpr int STAGE = 33024;
constexpr int SMEM_BYTES = 2 * STAGE;           // 66048
}

// conversion scratch (16 MB) + split-K partials (34 MB)
__device__ __align__(16) uint8_t g_KH[(size_t)Bb * NK * D * 2];
__device__ __align__(16) uint8_t g_KL[(size_t)Bb * NK * D * 2];
__device__ __align__(16) uint8_t g_VH[(size_t)Bb * NK * DV * 2];
__device__ __align__(16) uint8_t g_VL[(size_t)Bb * NK * DV * 2];
__device__ __align__(16) float   g_Op[(size_t)NSPLIT * Bb * NQ * DV];
__device__ __align__(16) float   g_lp[(size_t)NSPLIT * Bb * NQ];

__device__ __forceinline__ uint32_t smem_u32(const void* p) {
  uint32_t a;
  asm("{ .reg .u64 t; cvta.to.shared.u64 t, %1; cvt.u32.u64 %0, t; }" : "=r"(a) : "l"(p));
  return a;
}
__device__ __forceinline__ uint32_t packbf2(__nv_bfloat16 a, __nv_bfloat16 b) {
  __nv_bfloat162 t = __halves2bfloat162(a, b);
  return *reinterpret_cast<uint32_t*>(&t);
}
__device__ __forceinline__ void split2(float x, float y, uint32_t& hi, uint32_t& lo) {
  __nv_bfloat16 hx = __float2bfloat16(x), hy = __float2bfloat16(y);
  hi = packbf2(hx, hy);
  lo = packbf2(__float2bfloat16(x - __bfloat162float(hx)),
               __float2bfloat16(y - __bfloat162float(hy)));
}
__device__ __forceinline__ float ex2f(float x) {
  float y;
  asm("ex2.approx.ftz.f32 %0, %1;" : "=f"(y) : "f"(x));
  return y;
}
__device__ __forceinline__ void mma16816(float* c, const uint32_t* a,
                                         uint32_t b0, uint32_t b1) {
  asm volatile(
    "mma.sync.aligned.m16n8k16.row.col.f32.bf16.bf16.f32 "
    "{%0,%1,%2,%3}, {%4,%5,%6,%7}, {%8,%9}, {%0,%1,%2,%3};"
    : "+f"(c[0]), "+f"(c[1]), "+f"(c[2]), "+f"(c[3])
    : "r"(a[0]), "r"(a[1]), "r"(a[2]), "r"(a[3]), "r"(b0), "r"(b1));
}
__device__ __forceinline__ void ldsm4(uint32_t a, uint32_t* d) {
  asm volatile("ldmatrix.sync.aligned.m8n8.x4.shared.b16 {%0,%1,%2,%3}, [%4];"
               : "=r"(d[0]), "=r"(d[1]), "=r"(d[2]), "=r"(d[3]) : "r"(a));
}
__device__ __forceinline__ void ldsm4t(uint32_t a, uint32_t* d) {
  asm volatile("ldmatrix.sync.aligned.m8n8.x4.trans.shared.b16 {%0,%1,%2,%3}, [%4];"
               : "=r"(d[0]), "=r"(d[1]), "=r"(d[2]), "=r"(d[3]) : "r"(a));
}
__device__ __forceinline__ void cpasync16(uint32_t dst, const void* src) {
  asm volatile("cp.async.cg.shared.global [%0], [%1], 16;"
               :: "r"(dst), "l"(src) : "memory");
}
#define CP_COMMIT() asm volatile("cp.async.commit_group;" ::: "memory")
#define CP_WAIT1()  asm volatile("cp.async.wait_group 1;"  ::: "memory")

__device__ __forceinline__ uint32_t swz(uint32_t r, uint32_t cbyte) {
  return r * 128u + (cbyte ^ ((r & 7u) * 16u));
}

// ---------------- pre-pass ----------------
__global__ __launch_bounds__(256)
void convert_kernel(const float* __restrict__ K, const float* __restrict__ V) {
  const int idx = blockIdx.x * 256 + threadIdx.x;
  const int n = idx >> 4;
  const int c4 = idx & 15;
  const uint32_t r = (uint32_t)(n & 63);
  const size_t off = (size_t)(n >> 6) * 8192 + swz(r, (uint32_t)c4 * 8u);

  float4 kv = reinterpret_cast<const float4*>(K)[idx];
  uint2 hw, lw;
  split2(kv.x, kv.y, hw.x, lw.x);
  split2(kv.z, kv.w, hw.y, lw.y);
  *reinterpret_cast<uint2*>(g_KH + off) = hw;
  *reinterpret_cast<uint2*>(g_KL + off) = lw;

  float4 vv = reinterpret_cast<const float4*>(V)[idx];
  split2(vv.x, vv.y, hw.x, lw.x);
  split2(vv.z, vv.w, hw.y, lw.y);
  *reinterpret_cast<uint2*>(g_VH + off) = hw;
  *reinterpret_cast<uint2*>(g_VL + off) = lw;
}

// ---------------- main attention kernel (one key-quarter per CTA) ----------------
__global__ __launch_bounds__(THREADS, 2)
void attn_mma_kernel(const float* __restrict__ Q, const int* __restrict__ MQ,
                     const int* __restrict__ MK) {
  extern __shared__ char smem[];
  const uint32_t sb = smem_u32(smem);

  const int tid = threadIdx.x;
  const int w = tid >> 5, l = tid & 31;
  const int g = l >> 2, tg = l & 3;
  const int b = blockIdx.y;
  const int kq = blockIdx.z;                 // key quarter 0..3
  const int q0 = blockIdx.x * BM;
  const int row0 = q0 + w * 16 + g;
  const int row1 = row0 + 8;
  const uint32_t lrow = (uint32_t)(l & 7);
  const uint32_t ltile = (uint32_t)(l >> 3);
  const int* MKb = MK + (size_t)b * NK;

  // ---- Q fragments (persistent). Fold mask * log2e/T into Q.
  uint32_t QH[4][4], QL[4][4];
  {
    const float* Qr0 = Q + ((size_t)b * NQ + row0) * D;
    const float* Qr1 = Q + ((size_t)b * NQ + row1) * D;
    const float m0 = MQ[(size_t)b * NQ + row0] ? QSCALE : 0.f;
    const float m1 = MQ[(size_t)b * NQ + row1] ? QSCALE : 0.f;
    #pragma unroll
    for (int ks = 0; ks < 4; ks++) {
      const int c = 16 * ks + 2 * tg;
      float2 v00 = *reinterpret_cast<const float2*>(Qr0 + c);
      float2 v10 = *reinterpret_cast<const float2*>(Qr1 + c);
      float2 v01 = *reinterpret_cast<const float2*>(Qr0 + c + 8);
      float2 v11 = *reinterpret_cast<const float2*>(Qr1 + c + 8);
      split2(v00.x * m0, v00.y * m0, QH[ks][0], QL[ks][0]);
      split2(v10.x * m1, v10.y * m1, QH[ks][1], QL[ks][1]);
      split2(v01.x * m0, v01.y * m0, QH[ks][2], QL[ks][2]);
      split2(v11.x * m1, v11.y * m1, QH[ks][3], QL[ks][3]);
    }
  }

  float O[8][4];
  #pragma unroll
  for (int i = 0; i < 8; i++)
    #pragma unroll
    for (int j = 0; j < 4; j++) O[i][j] = 0.f;
  float l0 = 0.f, l1 = 0.f;

  // ---- prefetch: local tile t (0..NTQ-1) -> stage s
  auto prefetch = [&](int t, int s) {
    const uint32_t dst = sb + (uint32_t)s * STAGE;
    const int tg_ = kq * NTQ + t;            // global tile index
    const size_t toff = (size_t)(b * NT + tg_) * 8192;
    #pragma unroll
    for (int i = 0; i < 2; i++) {
      const uint32_t o = (uint32_t)(tid + i * THREADS) * 16u;
      cpasync16(dst + ST_KH + o, g_KH + toff + o);
      cpasync16(dst + ST_KL + o, g_KL + toff + o);
      cpasync16(dst + ST_VH + o, g_VH + toff + o);
      cpasync16(dst + ST_VL + o, g_VL + toff + o);
    }
    if (tid < 16) cpasync16(dst + ST_MK + tid * 16u, MKb + tg_ * BN + tid * 4);
  };

  prefetch(0, 0);
  CP_COMMIT();

  for (int t = 0; t < NTQ; t++) {
    const int s = t & 1;
    if (t + 1 < NTQ) prefetch(t + 1, (t + 1) & 1);
    CP_COMMIT();
    CP_WAIT1();
    __syncthreads();

    const uint32_t skh = sb + (uint32_t)s * STAGE + ST_KH;
    const uint32_t skl = sb + (uint32_t)s * STAGE + ST_KL;
    const uint32_t svh = sb + (uint32_t)s * STAGE + ST_VH;
    const uint32_t svl = sb + (uint32_t)s * STAGE + ST_VL;
    const int* mki = reinterpret_cast<const int*>(smem + (size_t)s * STAGE + ST_MK);

    // ---- S = Q @ K^T
    float S[8][4];
    #pragma unroll
    for (int i = 0; i < 8; i++)
      #pragma unroll
      for (int j = 0; j < 4; j++) S[i][j] = 0.f;

    #pragma unroll
    for (int nf = 0; nf < 8; nf++) {
      const uint32_t n = 8u * nf + lrow;
      const uint32_t a0 = swz(n, (8u * ltile) * 2u);
      const uint32_t a1 = swz(n, (32u + 8u * ltile) * 2u);
      uint32_t f[8];
      ldsm4(skh + a0, f);
      ldsm4(skh + a1, f + 4);
      #pragma unroll
      for (int ks = 0; ks < 4; ks++) {
        mma16816(S[nf], QH[ks], f[2 * ks], f[2 * ks + 1]);
        mma16816(S[nf], QL[ks], f[2 * ks], f[2 * ks + 1]);
      }
      ldsm4(skl + a0, f);
      ldsm4(skl + a1, f + 4);
      #pragma unroll
      for (int ks = 0; ks < 4; ks++)
        mma16816(S[nf], QH[ks], f[2 * ks], f[2 * ks + 1]);
    }

    // ---- softmax: p = exp2(S) * mk
    #pragma unroll
    for (int nf = 0; nf < 8; nf++) {
      const int c0 = 8 * nf + 2 * tg;
      const float mk0 = (float)mki[c0], mk1 = (float)mki[c0 + 1];
      float p0 = ex2f(S[nf][0]) * mk0;
      float p1 = ex2f(S[nf][1]) * mk1;
      float p2 = ex2f(S[nf][2]) * mk0;
      float p3 = ex2f(S[nf][3]) * mk1;
      l0 += p0 + p1; l1 += p2 + p3;
      S[nf][0] = p0; S[nf][1] = p1; S[nf][2] = p2; S[nf][3] = p3;
    }

    // ---- repack P (S-accumulator fragment layout == A-operand layout)
    uint32_t PH[4][4], PL[4][4];
    #pragma unroll
    for (int kc = 0; kc < 4; kc++) {
      split2(S[2 * kc][0],     S[2 * kc][1],     PH[kc][0], PL[kc][0]);
      split2(S[2 * kc][2],     S[2 * kc][3],     PH[kc][1], PL[kc][1]);
      split2(S[2 * kc + 1][0], S[2 * kc + 1][1], PH[kc][2], PL[kc][2]);
      split2(S[2 * kc + 1][2], S[2 * kc + 1][3], PH[kc][3], PL[kc][3]);
    }

    // ---- O += P @ V
    #pragma unroll
    for (int nf = 0; nf < 8; nf++) {
      const uint32_t r0 = 8u * ltile + lrow;
      const uint32_t r1 = 32u + 8u * ltile + lrow;
      const uint32_t a0 = swz(r0, 16u * nf);
      const uint32_t a1 = swz(r1, 16u * nf);
      uint32_t f[8];
      ldsm4t(svh + a0, f);
      ldsm4t(svh + a1, f + 4);
      #pragma unroll
      for (int kc = 0; kc < 4; kc++) {
        mma16816(O[nf], PH[kc], f[2 * kc], f[2 * kc + 1]);
        mma16816(O[nf], PL[kc], f[2 * kc], f[2 * kc + 1]);
      }
      ldsm4t(svl + a0, f);
      ldsm4t(svl + a1, f + 4);
      #pragma unroll
      for (int kc = 0; kc < 4; kc++)
        mma16816(O[nf], PH[kc], f[2 * kc], f[2 * kc + 1]);
    }
    __syncthreads();
  }

  // ---- write unnormalized partials + partial l
  l0 += __shfl_xor_sync(0xffffffffu, l0, 1);
  l0 += __shfl_xor_sync(0xffffffffu, l0, 2);
  l1 += __shfl_xor_sync(0xffffffffu, l1, 1);
  l1 += __shfl_xor_sync(0xffffffffu, l1, 2);

  const size_t pbase = (size_t)kq * Bb * NQ;
  float* O0 = g_Op + (pbase + (size_t)b * NQ + row0) * DV;
  float* O1 = g_Op + (pbase + (size_t)b * NQ + row1) * DV;
  #pragma unroll
  for (int nf = 0; nf < 8; nf++) {
    const int c = 8 * nf + 2 * tg;
    *reinterpret_cast<float2*>(O0 + c) = make_float2(O[nf][0], O[nf][1]);
    *reinterpret_cast<float2*>(O1 + c) = make_float2(O[nf][2], O[nf][3]);
  }
  if (tg == 0) {
    g_lp[pbase + (size_t)b * NQ + row0] = l0;
    g_lp[pbase + (size_t)b * NQ + row1] = l1;
  }
}

// ---------------- combine: Out = sum_z O_z / sum_z l_z ----------------
__global__ __launch_bounds__(256)
void combine_kernel(float* __restrict__ Out) {
  const int idx = blockIdx.x * 256 + threadIdx.x;   // one float4 of output
  const int grow = idx >> 4;                        // global row b*NQ + n
  float4 acc = make_float4(0.f, 0.f, 0.f, 0.f);
  float lsum = 0.f;
  #pragma unroll
  for (int z = 0; z < NSPLIT; z++) {
    const size_t o = (size_t)z * Bb * NQ * (DV / 4) + idx;
    float4 v = reinterpret_cast<const float4*>(g_Op)[o];
    acc.x += v.x; acc.y += v.y; acc.z += v.z; acc.w += v.w;
    lsum += g_lp[(size_t)z * Bb * NQ + grow];
  }
  const float inv = 1.0f / lsum;
  acc.x *= inv; acc.y *= inv; acc.z *= inv; acc.w *= inv;
  reinterpret_cast<float4*>(Out)[idx] = acc;
}

extern "C" void kernel_launch(void* const* d_in, const int* in_sizes, int n_in,
                              void* d_out, int out_size) {
  (void)in_sizes; (void)n_in; (void)out_size;
  const float* Q  = (const float*)d_in[0];
  const float* K  = (const float*)d_in[1];
  const float* V  = (const float*)d_in[2];
  const int*   MQ = (const int*)d_in[3];
  const int*   MK = (const int*)d_in[4];
  float* Out = (float*)d_out;

  convert_kernel<<<(Bb * NK * (D / 4)) / 256, 256>>>(K, V);

  cudaFuncSetAttribute(attn_mma_kernel,
                       cudaFuncAttributeMaxDynamicSharedMemorySize, SMEM_BYTES);
  dim3 grid(NQ / BM, Bb, NSPLIT);
  attn_mma_kernel<<<grid, THREADS, SMEM_BYTES>>>(Q, MQ, MK);

  combine_kernel<<<(Bb * NQ * DV / 4) / 256, 256>>>(Out);
}

// round 10
// speedup vs baseline: 1.5860x; 1.0062x over previous
#include <cuda_runtime.h>
#include <cuda_bf16.h>
#include <cstdint>

// ============================================================
// R10: split-K=4 + intra-tile chunk pipelining.
// Tile body reordered as S0,S1,softmax0,PV0,softmax1,PV1 so MUFU/repack
// bursts of one half overlap MMA streams of the other (in-order issue).
// Key mask pre-converted to float in the prepass.
// ============================================================

namespace {
constexpr int NQ = 4096, NK = 4096, D = 64, DV = 64, Bb = 8;
constexpr int BM = 128, BN = 64, THREADS = 256;
constexpr int NT = NK / BN;
constexpr int NSPLIT = 4;
constexpr int NTQ = NT / NSPLIT;                // 16 tiles per quarter
constexpr float QSCALE = 0.18033688011112042f;  // log2(e) / 8

constexpr int ST_KH = 0, ST_KL = 8192, ST_VH = 16384, ST_VL = 24576, ST_MK = 32768;
constexpr int STAGE = 33024;
constexpr int SMEM_BYTES = 2 * STAGE;
}

__device__ __align__(16) uint8_t g_KH[(size_t)Bb * NK * D * 2];
__device__ __align__(16) uint8_t g_KL[(size_t)Bb * NK * D * 2];
__device__ __align__(16) uint8_t g_VH[(size_t)Bb * NK * DV * 2];
__device__ __align__(16) uint8_t g_VL[(size_t)Bb * NK * DV * 2];
__device__ __align__(16) float   g_MKf[(size_t)Bb * NK];
__device__ __align__(16) float   g_Op[(size_t)NSPLIT * Bb * NQ * DV];
__device__ __align__(16) float   g_lp[(size_t)NSPLIT * Bb * NQ];

__device__ __forceinline__ uint32_t smem_u32(const void* p) {
  uint32_t a;
  asm("{ .reg .u64 t; cvta.to.shared.u64 t, %1; cvt.u32.u64 %0, t; }" : "=r"(a) : "l"(p));
  return a;
}
__device__ __forceinline__ uint32_t packbf2(__nv_bfloat16 a, __nv_bfloat16 b) {
  __nv_bfloat162 t = __halves2bfloat162(a, b);
  return *reinterpret_cast<uint32_t*>(&t);
}
__device__ __forceinline__ void split2(float x, float y, uint32_t& hi, uint32_t& lo) {
  __nv_bfloat16 hx = __float2bfloat16(x), hy = __float2bfloat16(y);
  hi = packbf2(hx, hy);
  lo = packbf2(__float2bfloat16(x - __bfloat162float(hx)),
               __float2bfloat16(y - __bfloat162float(hy)));
}
__device__ __forceinline__ float ex2f(float x) {
  float y;
  asm("ex2.approx.ftz.f32 %0, %1;" : "=f"(y) : "f"(x));
  return y;
}
__device__ __forceinline__ void mma16816(float* c, const uint32_t* a,
                                         uint32_t b0, uint32_t b1) {
  asm volatile(
    "mma.sync.aligned.m16n8k16.row.col.f32.bf16.bf16.f32 "
    "{%0,%1,%2,%3}, {%4,%5,%6,%7}, {%8,%9}, {%0,%1,%2,%3};"
    : "+f"(c[0]), "+f"(c[1]), "+f"(c[2]), "+f"(c[3])
    : "r"(a[0]), "r"(a[1]), "r"(a[2]), "r"(a[3]), "r"(b0), "r"(b1));
}
__device__ __forceinline__ void ldsm4(uint32_t a, uint32_t* d) {
  asm volatile("ldmatrix.sync.aligned.m8n8.x4.shared.b16 {%0,%1,%2,%3}, [%4];"
               : "=r"(d[0]), "=r"(d[1]), "=r"(d[2]), "=r"(d[3]) : "r"(a));
}
__device__ __forceinline__ void ldsm4t(uint32_t a, uint32_t* d) {
  asm volatile("ldmatrix.sync.aligned.m8n8.x4.trans.shared.b16 {%0,%1,%2,%3}, [%4];"
               : "=r"(d[0]), "=r"(d[1]), "=r"(d[2]), "=r"(d[3]) : "r"(a));
}
__device__ __forceinline__ void cpasync16(uint32_t dst, const void* src) {
  asm volatile("cp.async.cg.shared.global [%0], [%1], 16;"
               :: "r"(dst), "l"(src) : "memory");
}
#define CP_COMMIT() asm volatile("cp.async.commit_group;" ::: "memory")
#define CP_WAIT1()  asm volatile("cp.async.wait_group 1;"  ::: "memory")

__device__ __forceinline__ uint32_t swz(uint32_t r, uint32_t cbyte) {
  return r * 128u + (cbyte ^ ((r & 7u) * 16u));
}

// ---------------- pre-pass ----------------
__global__ __launch_bounds__(256)
void convert_kernel(const float* __restrict__ K, const float* __restrict__ V,
                    const int* __restrict__ MK) {
  const int idx = blockIdx.x * 256 + threadIdx.x;
  const int n = idx >> 4;
  const int c4 = idx & 15;
  const uint32_t r = (uint32_t)(n & 63);
  const size_t off = (size_t)(n >> 6) * 8192 + swz(r, (uint32_t)c4 * 8u);

  float4 kv = reinterpret_cast<const float4*>(K)[idx];
  uint2 hw, lw;
  split2(kv.x, kv.y, hw.x, lw.x);
  split2(kv.z, kv.w, hw.y, lw.y);
  *reinterpret_cast<uint2*>(g_KH + off) = hw;
  *reinterpret_cast<uint2*>(g_KL + off) = lw;

  float4 vv = reinterpret_cast<const float4*>(V)[idx];
  split2(vv.x, vv.y, hw.x, lw.x);
  split2(vv.z, vv.w, hw.y, lw.y);
  *reinterpret_cast<uint2*>(g_VH + off) = hw;
  *reinterpret_cast<uint2*>(g_VL + off) = lw;

  if (idx < Bb * NK / 4) {                       // mask int -> float
    int4 m = reinterpret_cast<const int4*>(MK)[idx];
    reinterpret_cast<float4*>(g_MKf)[idx] =
        make_float4((float)m.x, (float)m.y, (float)m.z, (float)m.w);
  }
}

// ---------------- main attention kernel ----------------
__global__ __launch_bounds__(THREADS, 2)
void attn_mma_kernel(const float* __restrict__ Q, const int* __restrict__ MQ) {
  extern __shared__ char smem[];
  const uint32_t sb = smem_u32(smem);

  const int tid = threadIdx.x;
  const int w = tid >> 5, l = tid & 31;
  const int g = l >> 2, tg = l & 3;
  const int b = blockIdx.y;
  const int kq = blockIdx.z;
  const int q0 = blockIdx.x * BM;
  const int row0 = q0 + w * 16 + g;
  const int row1 = row0 + 8;
  const uint32_t lrow = (uint32_t)(l & 7);
  const uint32_t ltile = (uint32_t)(l >> 3);
  const float* MKfb = g_MKf + (size_t)b * NK;

  // ---- Q fragments (persistent), mask*log2e/T folded in
  uint32_t QH[4][4], QL[4][4];
  {
    const float* Qr0 = Q + ((size_t)b * NQ + row0) * D;
    const float* Qr1 = Q + ((size_t)b * NQ + row1) * D;
    const float m0 = MQ[(size_t)b * NQ + row0] ? QSCALE : 0.f;
    const float m1 = MQ[(size_t)b * NQ + row1] ? QSCALE : 0.f;
    #pragma unroll
    for (int ks = 0; ks < 4; ks++) {
      const int c = 16 * ks + 2 * tg;
      float2 v00 = *reinterpret_cast<const float2*>(Qr0 + c);
      float2 v10 = *reinterpret_cast<const float2*>(Qr1 + c);
      float2 v01 = *reinterpret_cast<const float2*>(Qr0 + c + 8);
      float2 v11 = *reinterpret_cast<const float2*>(Qr1 + c + 8);
      split2(v00.x * m0, v00.y * m0, QH[ks][0], QL[ks][0]);
      split2(v10.x * m1, v10.y * m1, QH[ks][1], QL[ks][1]);
      split2(v01.x * m0, v01.y * m0, QH[ks][2], QL[ks][2]);
      split2(v11.x * m1, v11.y * m1, QH[ks][3], QL[ks][3]);
    }
  }

  float O[8][4];
  #pragma unroll
  for (int i = 0; i < 8; i++)
    #pragma unroll
    for (int j = 0; j < 4; j++) O[i][j] = 0.f;
  float l0 = 0.f, l1 = 0.f;

  auto prefetch = [&](int t, int s) {
    const uint32_t dst = sb + (uint32_t)s * STAGE;
    const int tg_ = kq * NTQ + t;
    const size_t toff = (size_t)(b * NT + tg_) * 8192;
    #pragma unroll
    for (int i = 0; i < 2; i++) {
      const uint32_t o = (uint32_t)(tid + i * THREADS) * 16u;
      cpasync16(dst + ST_KH + o, g_KH + toff + o);
      cpasync16(dst + ST_KL + o, g_KL + toff + o);
      cpasync16(dst + ST_VH + o, g_VH + toff + o);
      cpasync16(dst + ST_VL + o, g_VL + toff + o);
    }
    if (tid < 16) cpasync16(dst + ST_MK + tid * 16u, MKfb + tg_ * BN + tid * 4);
  };

  prefetch(0, 0);
  CP_COMMIT();

  for (int t = 0; t < NTQ; t++) {
    const int s = t & 1;
    if (t + 1 < NTQ) prefetch(t + 1, (t + 1) & 1);
    CP_COMMIT();
    CP_WAIT1();
    __syncthreads();

    const uint32_t skh = sb + (uint32_t)s * STAGE + ST_KH;
    const uint32_t skl = sb + (uint32_t)s * STAGE + ST_KL;
    const uint32_t svh = sb + (uint32_t)s * STAGE + ST_VH;
    const uint32_t svl = sb + (uint32_t)s * STAGE + ST_VL;
    const float* mkf = reinterpret_cast<const float*>(smem + (size_t)s * STAGE + ST_MK);

    float S[8][4];
    #pragma unroll
    for (int i = 0; i < 8; i++)
      #pragma unroll
      for (int j = 0; j < 4; j++) S[i][j] = 0.f;

    // ---- S-MMA, both chunks back-to-back (S1 issue hides S0 latency)
    #pragma unroll
    for (int nf = 0; nf < 8; nf++) {
      const uint32_t n = 8u * nf + lrow;
      const uint32_t a0 = swz(n, (8u * ltile) * 2u);
      const uint32_t a1 = swz(n, (32u + 8u * ltile) * 2u);
      uint32_t f[8];
      ldsm4(skh + a0, f);
      ldsm4(skh + a1, f + 4);
      #pragma unroll
      for (int ks = 0; ks < 4; ks++) {
        mma16816(S[nf], QH[ks], f[2 * ks], f[2 * ks + 1]);
        mma16816(S[nf], QL[ks], f[2 * ks], f[2 * ks + 1]);
      }
      ldsm4(skl + a0, f);
      ldsm4(skl + a1, f + 4);
      #pragma unroll
      for (int ks = 0; ks < 4; ks++)
        mma16816(S[nf], QH[ks], f[2 * ks], f[2 * ks + 1]);
    }

    // ---- two half-chunks: softmax(ch) then PV(ch); softmax(1) overlaps PV(0)
    #pragma unroll
    for (int ch = 0; ch < 2; ch++) {
      float* Sc = &S[4 * ch][0];          // S rows 4ch..4ch+3 (16 values)

      // softmax: p = exp2(S)*mk ; accumulate l
      #pragma unroll
      for (int j = 0; j < 4; j++) {
        const int c0 = 8 * (4 * ch + j) + 2 * tg;
        const float mk0 = mkf[c0], mk1 = mkf[c0 + 1];
        float p0 = ex2f(Sc[4 * j + 0]) * mk0;
        float p1 = ex2f(Sc[4 * j + 1]) * mk1;
        float p2 = ex2f(Sc[4 * j + 2]) * mk0;
        float p3 = ex2f(Sc[4 * j + 3]) * mk1;
        l0 += p0 + p1; l1 += p2 + p3;
        Sc[4 * j + 0] = p0; Sc[4 * j + 1] = p1;
        Sc[4 * j + 2] = p2; Sc[4 * j + 3] = p3;
      }

      // repack this chunk's P (kc = 2ch + j, j=0,1)
      uint32_t PH[2][4], PL[2][4];
      #pragma unroll
      for (int j = 0; j < 2; j++) {
        split2(Sc[8 * j + 0], Sc[8 * j + 1], PH[j][0], PL[j][0]);
        split2(Sc[8 * j + 2], Sc[8 * j + 3], PH[j][1], PL[j][1]);
        split2(Sc[8 * j + 4], Sc[8 * j + 5], PH[j][2], PL[j][2]);
        split2(Sc[8 * j + 6], Sc[8 * j + 7], PH[j][3], PL[j][3]);
      }

      // PV for this chunk: V rows 32ch..32ch+31 (kc pair), all 8 dv blocks
      const uint32_t vr = 32u * ch + 8u * ltile + lrow;
      #pragma unroll
      for (int nf = 0; nf < 8; nf++) {
        const uint32_t a = swz(vr, 16u * nf);
        uint32_t fh[4], fl[4];
        ldsm4t(svh + a, fh);
        ldsm4t(svl + a, fl);
        #pragma unroll
        for (int j = 0; j < 2; j++) {
          mma16816(O[nf], PH[j], fh[2 * j], fh[2 * j + 1]);
          mma16816(O[nf], PL[j], fh[2 * j], fh[2 * j + 1]);
          mma16816(O[nf], PH[j], fl[2 * j], fl[2 * j + 1]);
        }
      }
    }
    __syncthreads();
  }

  // ---- write unnormalized partials + partial l
  l0 += __shfl_xor_sync(0xffffffffu, l0, 1);
  l0 += __shfl_xor_sync(0xffffffffu, l0, 2);
  l1 += __shfl_xor_sync(0xffffffffu, l1, 1);
  l1 += __shfl_xor_sync(0xffffffffu, l1, 2);

  const size_t pbase = (size_t)kq * Bb * NQ;
  float* O0 = g_Op + (pbase + (size_t)b * NQ + row0) * DV;
  float* O1 = g_Op + (pbase + (size_t)b * NQ + row1) * DV;
  #pragma unroll
  for (int nf = 0; nf < 8; nf++) {
    const int c = 8 * nf + 2 * tg;
    *reinterpret_cast<float2*>(O0 + c) = make_float2(O[nf][0], O[nf][1]);
    *reinterpret_cast<float2*>(O1 + c) = make_float2(O[nf][2], O[nf][3]);
  }
  if (tg == 0) {
    g_lp[pbase + (size_t)b * NQ + row0] = l0;
    g_lp[pbase + (size_t)b * NQ + row1] = l1;
  }
}

// ---------------- combine ----------------
__global__ __launch_bounds__(256)
void combine_kernel(float* __restrict__ Out) {
  const int idx = blockIdx.x * 256 + threadIdx.x;
  const int grow = idx >> 4;
  float4 acc = make_float4(0.f, 0.f, 0.f, 0.f);
  float lsum = 0.f;
  #pragma unroll
  for (int z = 0; z < NSPLIT; z++) {
    const size_t o = (size_t)z * Bb * NQ * (DV / 4) + idx;
    float4 v = reinterpret_cast<const float4*>(g_Op)[o];
    acc.x += v.x; acc.y += v.y; acc.z += v.z; acc.w += v.w;
    lsum += g_lp[(size_t)z * Bb * NQ + grow];
  }
  const float inv = 1.0f / lsum;
  acc.x *= inv; acc.y *= inv; acc.z *= inv; acc.w *= inv;
  reinterpret_cast<float4*>(Out)[idx] = acc;
}

extern "C" void kernel_launch(void* const* d_in, const int* in_sizes, int n_in,
                              void* d_out, int out_size) {
  (void)in_sizes; (void)n_in; (void)out_size;
  const float* Q  = (const float*)d_in[0];
  const float* K  = (const float*)d_in[1];
  const float* V  = (const float*)d_in[2];
  const int*   MQ = (const int*)d_in[3];
  const int*   MK = (const int*)d_in[4];
  float* Out = (float*)d_out;

  convert_kernel<<<(Bb * NK * (D / 4)) / 256, 256>>>(K, V, MK);

  cudaFuncSetAttribute(attn_mma_kernel,
                       cudaFuncAttributeMaxDynamicSharedMemorySize, SMEM_BYTES);
  dim3 grid(NQ / BM, Bb, NSPLIT);
  attn_mma_kernel<<<grid, THREADS, SMEM_BYTES>>>(Q, MQ);

  combine_kernel<<<(Bb * NQ * DV / 4) / 256, 256>>>(Out);
}

// round 11
// speedup vs baseline: 1.6223x; 1.0229x over previous
#include <cuda_runtime.h>
#include <cuda_bf16.h>
#include <cstdint>

// ============================================================
// R11: split-K=4 warp-MMA flash attention, consolidated pipeline.
//  - 3-stage cp.async pipeline, ONE __syncthreads per tile
//    (wait -> sync -> prefetch(t+2) -> compute).
//  - P repack via PRMT truncation split (hi) + cvt.rn.bf16x2 (lo).
//  - mma asm non-volatile (register-pure) for scheduler freedom.
// Mainloop math identical: 3-product bf16 split, fixed-max softmax,
// O/l additive across 4 key quarters, combine kernel normalizes.
// ============================================================

namespace {
constexpr int NQ = 4096, NK = 4096, D = 64, DV = 64, Bb = 8;
constexpr int BM = 128, BN = 64, THREADS = 256;
constexpr int NT = NK / BN;
constexpr int NSPLIT = 4;
constexpr int NTQ = NT / NSPLIT;                // 16 tiles per quarter
constexpr float QSCALE = 0.18033688011112042f;  // log2(e) / 8

constexpr int ST_KH = 0, ST_KL = 8192, ST_VH = 16384, ST_VL = 24576, ST_MK = 32768;
constexpr int STAGE = 33024;
constexpr int NSTAGE = 3;
constexpr int SMEM_BYTES = NSTAGE * STAGE;      // 99072
}

__device__ __align__(16) uint8_t g_KH[(size_t)Bb * NK * D * 2];
__device__ __align__(16) uint8_t g_KL[(size_t)Bb * NK * D * 2];
__device__ __align__(16) uint8_t g_VH[(size_t)Bb * NK * DV * 2];
__device__ __align__(16) uint8_t g_VL[(size_t)Bb * NK * DV * 2];
__device__ __align__(16) float   g_MKf[(size_t)Bb * NK];
__device__ __align__(16) float   g_Op[(size_t)NSPLIT * Bb * NQ * DV];
__device__ __align__(16) float   g_lp[(size_t)NSPLIT * Bb * NQ];

__device__ __forceinline__ uint32_t smem_u32(const void* p) {
  uint32_t a;
  asm("{ .reg .u64 t; cvta.to.shared.u64 t, %1; cvt.u32.u64 %0, t; }" : "=r"(a) : "l"(p));
  return a;
}
__device__ __forceinline__ uint32_t packbf2(__nv_bfloat16 a, __nv_bfloat16 b) {
  __nv_bfloat162 t = __halves2bfloat162(a, b);
  return *reinterpret_cast<uint32_t*>(&t);
}
// RN split (prepass / Q only)
__device__ __forceinline__ void split2(float x, float y, uint32_t& hi, uint32_t& lo) {
  __nv_bfloat16 hx = __float2bfloat16(x), hy = __float2bfloat16(y);
  hi = packbf2(hx, hy);
  lo = packbf2(__float2bfloat16(x - __bfloat162float(hx)),
               __float2bfloat16(y - __bfloat162float(hy)));
}
// Truncation split (hot repack): hi = top16 bits of each float (PRMT),
// lo = rn-bf16 of exact residual. 3rd MMA product covers the coarser hi.
__device__ __forceinline__ void split2t(float x, float y, uint32_t& hi, uint32_t& lo) {
  const uint32_t xb = __float_as_uint(x), yb = __float_as_uint(y);
  asm("prmt.b32 %0, %1, %2, 0x7632;" : "=r"(hi) : "r"(xb), "r"(yb));
  const float xr = x - __uint_as_float(xb & 0xffff0000u);
  const float yr = y - __uint_as_float(yb & 0xffff0000u);
  asm("cvt.rn.bf16x2.f32 %0, %1, %2;" : "=r"(lo) : "f"(yr), "f"(xr));
}
__device__ __forceinline__ float ex2f(float x) {
  float y;
  asm("ex2.approx.ftz.f32 %0, %1;" : "=f"(y) : "f"(x));
  return y;
}
// register-pure: NOT volatile, lets the compiler interleave with FMA/MUFU work
__device__ __forceinline__ void mma16816(float* c, const uint32_t* a,
                                         uint32_t b0, uint32_t b1) {
  asm("mma.sync.aligned.m16n8k16.row.col.f32.bf16.bf16.f32 "
      "{%0,%1,%2,%3}, {%4,%5,%6,%7}, {%8,%9}, {%0,%1,%2,%3};"
      : "+f"(c[0]), "+f"(c[1]), "+f"(c[2]), "+f"(c[3])
      : "r"(a[0]), "r"(a[1]), "r"(a[2]), "r"(a[3]), "r"(b0), "r"(b1));
}
__device__ __forceinline__ void ldsm4(uint32_t a, uint32_t* d) {
  asm volatile("ldmatrix.sync.aligned.m8n8.x4.shared.b16 {%0,%1,%2,%3}, [%4];"
               : "=r"(d[0]), "=r"(d[1]), "=r"(d[2]), "=r"(d[3]) : "r"(a));
}
__device__ __forceinline__ void ldsm4t(uint32_t a, uint32_t* d) {
  asm volatile("ldmatrix.sync.aligned.m8n8.x4.trans.shared.b16 {%0,%1,%2,%3}, [%4];"
               : "=r"(d[0]), "=r"(d[1]), "=r"(d[2]), "=r"(d[3]) : "r"(a));
}
__device__ __forceinline__ void cpasync16(uint32_t dst, const void* src) {
  asm volatile("cp.async.cg.shared.global [%0], [%1], 16;"
               :: "r"(dst), "l"(src) : "memory");
}
#define CP_COMMIT() asm volatile("cp.async.commit_group;" ::: "memory")
#define CP_WAIT1()  asm volatile("cp.async.wait_group 1;"  ::: "memory")

__device__ __forceinline__ uint32_t swz(uint32_t r, uint32_t cbyte) {
  return r * 128u + (cbyte ^ ((r & 7u) * 16u));
}

// ---------------- pre-pass ----------------
__global__ __launch_bounds__(256)
void convert_kernel(const float* __restrict__ K, const float* __restrict__ V,
                    const int* __restrict__ MK) {
  const int idx = blockIdx.x * 256 + threadIdx.x;
  const int n = idx >> 4;
  const int c4 = idx & 15;
  const uint32_t r = (uint32_t)(n & 63);
  const size_t off = (size_t)(n >> 6) * 8192 + swz(r, (uint32_t)c4 * 8u);

  float4 kv = reinterpret_cast<const float4*>(K)[idx];
  uint2 hw, lw;
  split2(kv.x, kv.y, hw.x, lw.x);
  split2(kv.z, kv.w, hw.y, lw.y);
  *reinterpret_cast<uint2*>(g_KH + off) = hw;
  *reinterpret_cast<uint2*>(g_KL + off) = lw;

  float4 vv = reinterpret_cast<const float4*>(V)[idx];
  split2(vv.x, vv.y, hw.x, lw.x);
  split2(vv.z, vv.w, hw.y, lw.y);
  *reinterpret_cast<uint2*>(g_VH + off) = hw;
  *reinterpret_cast<uint2*>(g_VL + off) = lw;

  if (idx < Bb * NK / 4) {
    int4 m = reinterpret_cast<const int4*>(MK)[idx];
    reinterpret_cast<float4*>(g_MKf)[idx] =
        make_float4((float)m.x, (float)m.y, (float)m.z, (float)m.w);
  }
}

// ---------------- main attention kernel ----------------
__global__ __launch_bounds__(THREADS, 2)
void attn_mma_kernel(const float* __restrict__ Q, const int* __restrict__ MQ) {
  extern __shared__ char smem[];
  const uint32_t sb = smem_u32(smem);

  const int tid = threadIdx.x;
  const int w = tid >> 5, l = tid & 31;
  const int g = l >> 2, tg = l & 3;
  const int b = blockIdx.y;
  const int kq = blockIdx.z;
  const int q0 = blockIdx.x * BM;
  const int row0 = q0 + w * 16 + g;
  const int row1 = row0 + 8;
  const uint32_t lrow = (uint32_t)(l & 7);
  const uint32_t ltile = (uint32_t)(l >> 3);
  const float* MKfb = g_MKf + (size_t)b * NK;

  // ---- Q fragments (persistent), mask*log2e/T folded in
  uint32_t QH[4][4], QL[4][4];
  {
    const float* Qr0 = Q + ((size_t)b * NQ + row0) * D;
    const float* Qr1 = Q + ((size_t)b * NQ + row1) * D;
    const float m0 = MQ[(size_t)b * NQ + row0] ? QSCALE : 0.f;
    const float m1 = MQ[(size_t)b * NQ + row1] ? QSCALE : 0.f;
    #pragma unroll
    for (int ks = 0; ks < 4; ks++) {
      const int c = 16 * ks + 2 * tg;
      float2 v00 = *reinterpret_cast<const float2*>(Qr0 + c);
      float2 v10 = *reinterpret_cast<const float2*>(Qr1 + c);
      float2 v01 = *reinterpret_cast<const float2*>(Qr0 + c + 8);
      float2 v11 = *reinterpret_cast<const float2*>(Qr1 + c + 8);
      split2(v00.x * m0, v00.y * m0, QH[ks][0], QL[ks][0]);
      split2(v10.x * m1, v10.y * m1, QH[ks][1], QL[ks][1]);
      split2(v01.x * m0, v01.y * m0, QH[ks][2], QL[ks][2]);
      split2(v11.x * m1, v11.y * m1, QH[ks][3], QL[ks][3]);
    }
  }

  float O[8][4];
  #pragma unroll
  for (int i = 0; i < 8; i++)
    #pragma unroll
    for (int j = 0; j < 4; j++) O[i][j] = 0.f;
  float l0 = 0.f, l1 = 0.f;

  auto prefetch = [&](int t, int s) {
    const uint32_t dst = sb + (uint32_t)s * STAGE;
    const int tg_ = kq * NTQ + t;
    const size_t toff = (size_t)(b * NT + tg_) * 8192;
    #pragma unroll
    for (int i = 0; i < 2; i++) {
      const uint32_t o = (uint32_t)(tid + i * THREADS) * 16u;
      cpasync16(dst + ST_KH + o, g_KH + toff + o);
      cpasync16(dst + ST_KL + o, g_KL + toff + o);
      cpasync16(dst + ST_VH + o, g_VH + toff + o);
      cpasync16(dst + ST_VL + o, g_VL + toff + o);
    }
    if (tid < 16) cpasync16(dst + ST_MK + tid * 16u, MKfb + tg_ * BN + tid * 4);
  };

  // prologue: stages 0 and 1 in flight
  prefetch(0, 0);
  CP_COMMIT();
  prefetch(1, 1);
  CP_COMMIT();

  for (int t = 0; t < NTQ; t++) {
    const int s = t % NSTAGE;
    CP_WAIT1();          // group t retired => stage s ready (my copies)
    __syncthreads();     // everyone's copies visible; prior readers of s+2 done

    if (t + 2 < NTQ) prefetch(t + 2, (t + 2) % NSTAGE);
    CP_COMMIT();         // uniform group accounting

    const uint32_t skh = sb + (uint32_t)s * STAGE + ST_KH;
    const uint32_t skl = sb + (uint32_t)s * STAGE + ST_KL;
    const uint32_t svh = sb + (uint32_t)s * STAGE + ST_VH;
    const uint32_t svl = sb + (uint32_t)s * STAGE + ST_VL;
    const float* mkf = reinterpret_cast<const float*>(smem + (size_t)s * STAGE + ST_MK);

    float S[8][4];
    #pragma unroll
    for (int i = 0; i < 8; i++)
      #pragma unroll
      for (int j = 0; j < 4; j++) S[i][j] = 0.f;

    // ---- S = Q @ K^T (3-product bf16 split)
    #pragma unroll
    for (int nf = 0; nf < 8; nf++) {
      const uint32_t n = 8u * nf + lrow;
      const uint32_t a0 = swz(n, (8u * ltile) * 2u);
      const uint32_t a1 = swz(n, (32u + 8u * ltile) * 2u);
      uint32_t f[8];
      ldsm4(skh + a0, f);
      ldsm4(skh + a1, f + 4);
      #pragma unroll
      for (int ks = 0; ks < 4; ks++) {
        mma16816(S[nf], QH[ks], f[2 * ks], f[2 * ks + 1]);
        mma16816(S[nf], QL[ks], f[2 * ks], f[2 * ks + 1]);
      }
      ldsm4(skl + a0, f);
      ldsm4(skl + a1, f + 4);
      #pragma unroll
      for (int ks = 0; ks < 4; ks++)
        mma16816(S[nf], QH[ks], f[2 * ks], f[2 * ks + 1]);
    }

    // ---- two half-chunks: softmax(ch) -> repack -> PV(ch)
    #pragma unroll
    for (int ch = 0; ch < 2; ch++) {
      float* Sc = &S[4 * ch][0];

      #pragma unroll
      for (int j = 0; j < 4; j++) {
        const int c0 = 8 * (4 * ch + j) + 2 * tg;
        const float mk0 = mkf[c0], mk1 = mkf[c0 + 1];
        float p0 = ex2f(Sc[4 * j + 0]) * mk0;
        float p1 = ex2f(Sc[4 * j + 1]) * mk1;
        float p2 = ex2f(Sc[4 * j + 2]) * mk0;
        float p3 = ex2f(Sc[4 * j + 3]) * mk1;
        l0 += p0 + p1; l1 += p2 + p3;
        Sc[4 * j + 0] = p0; Sc[4 * j + 1] = p1;
        Sc[4 * j + 2] = p2; Sc[4 * j + 3] = p3;
      }

      uint32_t PH[2][4], PL[2][4];
      #pragma unroll
      for (int j = 0; j < 2; j++) {
        split2t(Sc[8 * j + 0], Sc[8 * j + 1], PH[j][0], PL[j][0]);
        split2t(Sc[8 * j + 2], Sc[8 * j + 3], PH[j][1], PL[j][1]);
        split2t(Sc[8 * j + 4], Sc[8 * j + 5], PH[j][2], PL[j][2]);
        split2t(Sc[8 * j + 6], Sc[8 * j + 7], PH[j][3], PL[j][3]);
      }

      const uint32_t vr = 32u * ch + 8u * ltile + lrow;
      #pragma unroll
      for (int nf = 0; nf < 8; nf++) {
        const uint32_t a = swz(vr, 16u * nf);
        uint32_t fh[4], fl[4];
        ldsm4t(svh + a, fh);
        ldsm4t(svl + a, fl);
        #pragma unroll
        for (int j = 0; j < 2; j++) {
          mma16816(O[nf], PH[j], fh[2 * j], fh[2 * j + 1]);
          mma16816(O[nf], PL[j], fh[2 * j], fh[2 * j + 1]);
          mma16816(O[nf], PH[j], fl[2 * j], fl[2 * j + 1]);
        }
      }
    }
  }

  // ---- write unnormalized partials + partial l
  l0 += __shfl_xor_sync(0xffffffffu, l0, 1);
  l0 += __shfl_xor_sync(0xffffffffu, l0, 2);
  l1 += __shfl_xor_sync(0xffffffffu, l1, 1);
  l1 += __shfl_xor_sync(0xffffffffu, l1, 2);

  const size_t pbase = (size_t)kq * Bb * NQ;
  float* O0 = g_Op + (pbase + (size_t)b * NQ + row0) * DV;
  float* O1 = g_Op + (pbase + (size_t)b * NQ + row1) * DV;
  #pragma unroll
  for (int nf = 0; nf < 8; nf++) {
    const int c = 8 * nf + 2 * tg;
    *reinterpret_cast<float2*>(O0 + c) = make_float2(O[nf][0], O[nf][1]);
    *reinterpret_cast<float2*>(O1 + c) = make_float2(O[nf][2], O[nf][3]);
  }
  if (tg == 0) {
    g_lp[pbase + (size_t)b * NQ + row0] = l0;
    g_lp[pbase + (size_t)b * NQ + row1] = l1;
  }
}

// ---------------- combine ----------------
__global__ __launch_bounds__(256)
void combine_kernel(float* __restrict__ Out) {
  const int idx = blockIdx.x * 256 + threadIdx.x;
  const int grow = idx >> 4;
  float4 acc = make_float4(0.f, 0.f, 0.f, 0.f);
  float lsum = 0.f;
  #pragma unroll
  for (int z = 0; z < NSPLIT; z++) {
    const size_t o = (size_t)z * Bb * NQ * (DV / 4) + idx;
    float4 v = reinterpret_cast<const float4*>(g_Op)[o];
    acc.x += v.x; acc.y += v.y; acc.z += v.z; acc.w += v.w;
    lsum += g_lp[(size_t)z * Bb * NQ + grow];
  }
  const float inv = 1.0f / lsum;
  acc.x *= inv; acc.y *= inv; acc.z *= inv; acc.w *= inv;
  reinterpret_cast<float4*>(Out)[idx] = acc;
}

extern "C" void kernel_launch(void* const* d_in, const int* in_sizes, int n_in,
                              void* d_out, int out_size) {
  (void)in_sizes; (void)n_in; (void)out_size;
  const float* Q  = (const float*)d_in[0];
  const float* K  = (const float*)d_in[1];
  const float* V  = (const float*)d_in[2];
  const int*   MQ = (const int*)d_in[3];
  const int*   MK = (const int*)d_in[4];
  float* Out = (float*)d_out;

  convert_kernel<<<(Bb * NK * (D / 4)) / 256, 256>>>(K, V, MK);

  cudaFuncSetAttribute(attn_mma_kernel,
                       cudaFuncAttributeMaxDynamicSharedMemorySize, SMEM_BYTES);
  dim3 grid(NQ / BM, Bb, NSPLIT);
  attn_mma_kernel<<<grid, THREADS, SMEM_BYTES>>>(Q, MQ);

  combine_kernel<<<(Bb * NQ * DV / 4) / 256, 256>>>(Out);
}